// round 8
// baseline (speedup 1.0000x reference)
#include <cuda_runtime.h>

#define NIN 7
#define H   32
#define TPB 128   // threads per block
#define SPT 2     // samples per thread

typedef unsigned long long u64;

// Constant-bank weight image, float4-granular:
//  [0,56)    w0t  : w0t[i*8+c] covers floats i*32 + 4c .. +3  (w0 transposed [i][h])
//  [56,312)  w1t  : w1t[i*8+c]                                 (w1 transposed [i][h])
//  [312,320) b0   (32 floats)
//  [320,328) b1   (32 floats)
//  [328,336) w2   (32 floats)
//  [336]     b2 in .x
__constant__ float4 CW4[337];
__device__ float DSTG[1348];

typedef union { float4 f; ulonglong2 u; } F4U;

__device__ __forceinline__ ulonglong2 ldc4(int idx) {
    F4U t; t.f = CW4[idx]; return t.u;
}

// ---- f32x2 packed helpers (sm_100+ PTX) ----
__device__ __forceinline__ u64 pk2(float a, float b) {
    u64 r; asm("mov.b64 %0, {%1, %2};" : "=l"(r) : "f"(a), "f"(b)); return r;
}
__device__ __forceinline__ float2 upk2(u64 v) {
    float2 f; asm("mov.b64 {%0, %1}, %2;" : "=f"(f.x), "=f"(f.y) : "l"(v)); return f;
}
__device__ __forceinline__ u64 ffma2(u64 a, u64 b, u64 c) {
    u64 r; asm("fma.rn.f32x2 %0, %1, %2, %3;" : "=l"(r) : "l"(a), "l"(b), "l"(c)); return r;
}

// Single-instruction MUFU.TANH (sm_75+).
__device__ __forceinline__ float tanh_approx(float x) {
    float r; asm("tanh.approx.f32 %0, %1;" : "=f"(r) : "f"(x)); return r;
}

// Transpose weights into the staging layout (then memcpy'd into CW4).
__global__ void prep_kernel(const float* __restrict__ w0, const float* __restrict__ b0,
                            const float* __restrict__ w1, const float* __restrict__ b1,
                            const float* __restrict__ w2, const float* __restrict__ b2)
{
    int k = blockIdx.x * blockDim.x + threadIdx.x;
    if (k < 224) {                       // w0t[i*32+h] = w0[h][i]
        int i = k >> 5, h = k & 31;
        DSTG[k] = w0[h * NIN + i];
    } else if (k < 1248) {               // w1t[i*32+h] = w1[h][i]
        int kk = k - 224;
        int i = kk >> 5, h = kk & 31;
        DSTG[k] = w1[h * H + i];
    } else if (k < 1280) DSTG[k] = b0[k - 1248];
    else if (k < 1312)   DSTG[k] = b1[k - 1280];
    else if (k < 1344)   DSTG[k] = w2[k - 1312];
    else if (k < 1348)   DSTG[k] = b2[0];
}

__global__ __launch_bounds__(TPB, 5)
void WarpTileMLP_kernel(const float* __restrict__ q, float* __restrict__ out)
{
    const int tid = threadIdx.x;
    const long t = (long)blockIdx.x * TPB + tid;

    // 2 samples = 14 contiguous floats = 7 aligned float2 loads.
    const float2* qv = (const float2*)q;
    float v[14];
#pragma unroll
    for (int j = 0; j < 7; ++j) {
        float2 p = __ldg(&qv[t * 7 + j]);
        v[2 * j] = p.x; v[2 * j + 1] = p.y;
    }
    // sample A = v[0..6], sample B = v[7..13]

    // -------- Layer 0: 7 -> 32, in two 16-unit halves (lower reg pressure) ---
    float zA[H], zB[H];
#pragma unroll
    for (int half = 0; half < 2; ++half) {
        u64 accA[8], accB[8];
#pragma unroll
        for (int pp = 0; pp < 4; ++pp) {
            ulonglong2 bb = ldc4(312 + half * 4 + pp);
            accA[2 * pp]     = bb.x; accB[2 * pp]     = bb.x;
            accA[2 * pp + 1] = bb.y; accB[2 * pp + 1] = bb.y;
        }
#pragma unroll
        for (int i = 0; i < NIN; ++i) {
            u64 xa = pk2(v[i], v[i]);
            u64 xb = pk2(v[7 + i], v[7 + i]);
#pragma unroll
            for (int c = 0; c < 4; ++c) {
                ulonglong2 w = ldc4(i * 8 + half * 4 + c);
                accA[2 * c]     = ffma2(w.x, xa, accA[2 * c]);
                accA[2 * c + 1] = ffma2(w.y, xa, accA[2 * c + 1]);
                accB[2 * c]     = ffma2(w.x, xb, accB[2 * c]);
                accB[2 * c + 1] = ffma2(w.y, xb, accB[2 * c + 1]);
            }
        }
        // tanh -> z (half accs die here)
#pragma unroll
        for (int p = 0; p < 8; ++p) {
            int h0 = half * 16 + 2 * p;
            float2 a = upk2(accA[p]);
            zA[h0] = tanh_approx(a.x); zA[h0 + 1] = tanh_approx(a.y);
            float2 b = upk2(accB[p]);
            zB[h0] = tanh_approx(b.x); zB[h0 + 1] = tanh_approx(b.y);
        }
    }

    // ---- Layer 1 fused with Layer 2, in four quarters of 8 hidden units ----
    u64 oA = pk2(0.0f, 0.0f);
    u64 oB = pk2(0.0f, 0.0f);

#pragma unroll
    for (int qtr = 0; qtr < 4; ++qtr) {
        u64 a1A[4], a1B[4];
        {
            ulonglong2 b0p = ldc4(320 + qtr * 2);
            ulonglong2 b1p = ldc4(320 + qtr * 2 + 1);
            a1A[0] = b0p.x; a1A[1] = b0p.y; a1A[2] = b1p.x; a1A[3] = b1p.y;
            a1B[0] = b0p.x; a1B[1] = b0p.y; a1B[2] = b1p.x; a1B[3] = b1p.y;
        }
#pragma unroll
        for (int i = 0; i < H; ++i) {
            u64 xa = pk2(zA[i], zA[i]);
            u64 xb = pk2(zB[i], zB[i]);
#pragma unroll
            for (int c = 0; c < 2; ++c) {
                ulonglong2 w = ldc4(56 + i * 8 + qtr * 2 + c);
                a1A[2 * c]     = ffma2(w.x, xa, a1A[2 * c]);
                a1A[2 * c + 1] = ffma2(w.y, xa, a1A[2 * c + 1]);
                a1B[2 * c]     = ffma2(w.x, xb, a1B[2 * c]);
                a1B[2 * c + 1] = ffma2(w.y, xb, a1B[2 * c + 1]);
            }
        }
        // tanh + layer-2 partial dot (a1 dies here)
        ulonglong2 w2a = ldc4(328 + qtr * 2);
        ulonglong2 w2b = ldc4(328 + qtr * 2 + 1);
        u64 wps[4] = { w2a.x, w2a.y, w2b.x, w2b.y };
#pragma unroll
        for (int p = 0; p < 4; ++p) {
            u64 wp = wps[p];
            float2 a = upk2(a1A[p]);
            u64 za = pk2(tanh_approx(a.x), tanh_approx(a.y));
            oA = ffma2(wp, za, oA);
            float2 b = upk2(a1B[p]);
            u64 zb = pk2(tanh_approx(b.x), tanh_approx(b.y));
            oB = ffma2(wp, zb, oB);
        }
    }

    float2 ra = upk2(oA);
    float2 rb = upk2(oB);
    float bias2;
    { F4U tb; tb.f = CW4[336]; bias2 = tb.f.x; }
    float outA = ra.x + ra.y + bias2;
    float outB = rb.x + rb.y + bias2;

    ((float2*)out)[t] = make_float2(outA, outB);
}

extern "C" void kernel_launch(void* const* d_in, const int* in_sizes, int n_in,
                              void* d_out, int out_size)
{
    const float* q  = (const float*)d_in[0];
    const float* w0 = (const float*)d_in[1];
    const float* b0 = (const float*)d_in[2];
    const float* w1 = (const float*)d_in[3];
    const float* b1 = (const float*)d_in[4];
    const float* w2 = (const float*)d_in[5];
    const float* b2 = (const float*)d_in[6];
    float* out = (float*)d_out;

    // 1) transpose weights into staging (device global)
    prep_kernel<<<11, TPB>>>(w0, b0, w1, b1, w2, b2);

    // 2) copy staging -> constant bank (D2D memcpy node; graph-capturable)
    void* sym = nullptr; void* stg = nullptr;
    cudaGetSymbolAddress(&sym, CW4);
    cudaGetSymbolAddress(&stg, DSTG);
    cudaMemcpyAsync(sym, stg, 1348 * sizeof(float), cudaMemcpyDeviceToDevice);

    // 3) main kernel
    const int B = in_sizes[0] / NIN;              // 2097152
    const int blocks = B / (TPB * SPT);           // 8192
    WarpTileMLP_kernel<<<blocks, TPB>>>(q, out);
}

// round 9
// speedup vs baseline: 1.4167x; 1.4167x over previous
#include <cuda_runtime.h>
#include <cuda_bf16.h>
#include <cstdint>

#define NIN 7
#define H   32
#define TPB 128
#define ITERS 4          // 128 samples per CTA per iter

typedef unsigned long long u64;
typedef unsigned int u32;

// ---------------- constant weight image (same layout as R6 champion) --------
//  float4 idx: [0,56) w0t pairs ; [312,320) b0 ; floats: b1 @1280, w2 @1312, b2 @1344
__constant__ float4 CW4[337];
__device__ float DSTG[1348];
// B fragments for mma.m16n8k16 (per-lane, PTX fragment layout):
// tile t = hl*8 + kt*4 + nt  (hl: 0=W_hi,1=W_lo ; kt: k16-tile 0..1 ; nt: n8-tile 0..3)
// BFG[t*32 + lane] = {b0b1, b2b3}
__device__ uint2 BFG[512];

typedef union { float4 f; ulonglong2 u; } F4U;
__device__ __forceinline__ ulonglong2 ldc4(int idx) { F4U t; t.f = CW4[idx]; return t.u; }
__device__ __forceinline__ float cwf(int fidx) { return ((const float*)CW4)[fidx]; }

// ---------------- scalar helpers ----------------
__device__ __forceinline__ u64 pk2(float a, float b) {
    u64 r; asm("mov.b64 %0, {%1, %2};" : "=l"(r) : "f"(a), "f"(b)); return r;
}
__device__ __forceinline__ float2 upk2(u64 v) {
    float2 f; asm("mov.b64 {%0, %1}, %2;" : "=f"(f.x), "=f"(f.y) : "l"(v)); return f;
}
__device__ __forceinline__ u64 ffma2(u64 a, u64 b, u64 c) {
    u64 r; asm("fma.rn.f32x2 %0, %1, %2, %3;" : "=l"(r) : "l"(a), "l"(b), "l"(c)); return r;
}
__device__ __forceinline__ float tanh_approx(float x) {
    float r; asm("tanh.approx.f32 %0, %1;" : "=f"(r) : "f"(x)); return r;
}
// lower 16 bits = bf16(a), upper = bf16(b)
__device__ __forceinline__ u32 bf16x2_of(float a, float b) {
    u32 r; asm("cvt.rn.bf16x2.f32 %0, %1, %2;" : "=r"(r) : "f"(b), "f"(a)); return r;
}
__device__ __forceinline__ u32 smem_u32(const void* p) {
    u32 a; asm("{ .reg .u64 t; cvta.to.shared.u64 t, %1; cvt.u32.u64 %0, t; }"
               : "=r"(a) : "l"(p));
    return a;
}
__device__ __forceinline__ void ldsm4(u32* r, u32 addr) {
    asm volatile("ldmatrix.sync.aligned.m8n8.x4.shared.b16 {%0,%1,%2,%3}, [%4];"
                 : "=r"(r[0]), "=r"(r[1]), "=r"(r[2]), "=r"(r[3]) : "r"(addr));
}
__device__ __forceinline__ void mma_bf16(float* d, const u32* a, uint2 b) {
    asm volatile(
        "mma.sync.aligned.m16n8k16.row.col.f32.bf16.bf16.f32 "
        "{%0,%1,%2,%3}, {%4,%5,%6,%7}, {%8,%9}, {%0,%1,%2,%3};"
        : "+f"(d[0]), "+f"(d[1]), "+f"(d[2]), "+f"(d[3])
        : "r"(a[0]), "r"(a[1]), "r"(a[2]), "r"(a[3]), "r"(b.x), "r"(b.y));
}

// ---------------- prep kernel ----------------
__global__ void prep_kernel(const float* __restrict__ w0, const float* __restrict__ b0,
                            const float* __restrict__ w1, const float* __restrict__ b1,
                            const float* __restrict__ w2, const float* __restrict__ b2)
{
    int g = blockIdx.x * blockDim.x + threadIdx.x;
    int stride = gridDim.x * blockDim.x;

    for (int k = g; k < 1348; k += stride) {
        if (k < 224) {                       // w0t[i*32+h] = w0[h][i]
            int i = k >> 5, h = k & 31;
            DSTG[k] = w0[h * NIN + i];
        } else if (k < 1248) {               // w1t (layout stability, unused)
            int kk = k - 224;
            int i = kk >> 5, h = kk & 31;
            DSTG[k] = w1[h * H + i];
        } else if (k < 1280) DSTG[k] = b0[k - 1248];
        else if (k < 1312)   DSTG[k] = b1[k - 1280];
        else if (k < 1344)   DSTG[k] = w2[k - 1312];
        else                 DSTG[k] = b2[0];
    }

    // B fragments: B[k][n] = w1[n][k]; per-lane frag values (PTX m16n8k16 layout):
    //   b0b1 = (B[k0][n], B[k0+1][n]), b2b3 = (B[k0+8][n], B[k0+9][n])
    //   n = 8*nt + lane/4 ; k0 = 16*kt + 2*(lane%4)
    for (int idx = g; idx < 512; idx += stride) {
        int t = idx >> 5, l = idx & 31;
        int hl = t >> 3, kt = (t >> 2) & 1, nt = t & 3;
        int n = 8 * nt + (l >> 2);
        int k0 = 16 * kt + 2 * (l & 3);

        float wv[4];
        int ks[4] = { k0, k0 + 1, k0 + 8, k0 + 9 };
        u32 p[4];
        for (int j = 0; j < 4; ++j) {
            float w = w1[n * H + ks[j]];
            __nv_bfloat16 hi = __float2bfloat16(w);
            if (hl == 0) {
                union { __nv_bfloat16 h; unsigned short s; } c; c.h = hi; p[j] = c.s;
            } else {
                __nv_bfloat16 lo = __float2bfloat16(w - __bfloat162float(hi));
                union { __nv_bfloat16 h; unsigned short s; } c; c.h = lo; p[j] = c.s;
            }
            (void)wv;
        }
        BFG[idx] = make_uint2(p[0] | (p[1] << 16), p[2] | (p[3] << 16));
    }
}

// ---------------- main kernel ----------------
__global__ __launch_bounds__(TPB, 4)
void WarpTileMLP_kernel(const float* __restrict__ q, float* __restrict__ out)
{
    // per-warp staging: Z_hi 32x32 bf16 (rows of 64B) + Z_lo, XOR-swizzled chunks
    __shared__ __align__(16) char zstage[4][4096];

    const int tid  = threadIdx.x;
    const int wid  = tid >> 5;
    const int lane = tid & 31;

    const u32 zh = smem_u32(&zstage[wid][0]);
    const u32 zl = zh + 2048;

    // STS offsets: row = lane, chunk c stored at c ^ ((row>>1)&3)
    u32 sts_off[4];
#pragma unroll
    for (int c = 0; c < 4; ++c)
        sts_off[c] = (u32)lane * 64u + (u32)((c ^ ((lane >> 1) & 3)) * 16);

    // ldmatrix offsets for A tile (mt, kt): lane -> (row, chunk)
    u32 lds_off[2][2];
    {
        int r16 = lane & 15, cb = lane >> 4;
#pragma unroll
        for (int mt = 0; mt < 2; ++mt)
#pragma unroll
            for (int kt = 0; kt < 2; ++kt)
                lds_off[mt][kt] = (u32)((16 * mt + r16) * 64 +
                                        (((2 * kt + cb) ^ ((r16 >> 1) & 3)) * 16));
    }

    // per-lane b1/w2 for epilogue columns: col(nt,j) = 8nt + 2*(lane&3) + j
    float b1c[8], w2c[8];
#pragma unroll
    for (int nt = 0; nt < 4; ++nt)
#pragma unroll
        for (int j = 0; j < 2; ++j) {
            int col = 8 * nt + 2 * (lane & 3) + j;
            b1c[nt * 2 + j] = cwf(1280 + col);
            w2c[nt * 2 + j] = cwf(1312 + col);
        }
    const float b2v = cwf(1344);

    for (int it = 0; it < ITERS; ++it) {
        const long sbase = (((long)blockIdx.x * ITERS + it) * TPB) + wid * 32;
        const long s = sbase + lane;

        // ---- layer 0 (1 sample/thread), constant weights, f32x2 ----
        float x[NIN];
        const float* qr = q + s * NIN;
#pragma unroll
        for (int i = 0; i < NIN; ++i) x[i] = __ldg(qr + i);

        u64 acc[16];
#pragma unroll
        for (int pp = 0; pp < 8; ++pp) {
            ulonglong2 bb = ldc4(312 + pp);
            acc[2 * pp] = bb.x; acc[2 * pp + 1] = bb.y;
        }
#pragma unroll
        for (int i = 0; i < NIN; ++i) {
            u64 xd = pk2(x[i], x[i]);
#pragma unroll
            for (int c = 0; c < 8; ++c) {
                ulonglong2 w = ldc4(i * 8 + c);
                acc[2 * c]     = ffma2(w.x, xd, acc[2 * c]);
                acc[2 * c + 1] = ffma2(w.y, xd, acc[2 * c + 1]);
            }
        }

        // ---- tanh -> bf16 hi/lo split ----
        u32 hib[16], lob[16];
#pragma unroll
        for (int p = 0; p < 16; ++p) {
            float2 z = upk2(acc[p]);
            float t0 = tanh_approx(z.x), t1 = tanh_approx(z.y);
            u32 hi = bf16x2_of(t0, t1);
            float h0 = __uint_as_float(hi << 16);
            float h1 = __uint_as_float(hi & 0xFFFF0000u);
            hib[p] = hi;
            lob[p] = bf16x2_of(t0 - h0, t1 - h1);
        }

        // ---- stage to warp-private smem (swizzled 16B chunks) ----
#pragma unroll
        for (int c = 0; c < 4; ++c) {
            asm volatile("st.shared.v4.b32 [%0], {%1,%2,%3,%4};" ::
                "r"(zh + sts_off[c]), "r"(hib[4*c]), "r"(hib[4*c+1]),
                "r"(hib[4*c+2]), "r"(hib[4*c+3]) : "memory");
            asm volatile("st.shared.v4.b32 [%0], {%1,%2,%3,%4};" ::
                "r"(zl + sts_off[c]), "r"(lob[4*c]), "r"(lob[4*c+1]),
                "r"(lob[4*c+2]), "r"(lob[4*c+3]) : "memory");
        }
        __syncwarp();

        // ---- load A fragments ----
        u32 AH[2][2][4], AL[2][2][4];
#pragma unroll
        for (int mt = 0; mt < 2; ++mt)
#pragma unroll
            for (int kt = 0; kt < 2; ++kt) {
                ldsm4(AH[mt][kt], zh + lds_off[mt][kt]);
                ldsm4(AL[mt][kt], zl + lds_off[mt][kt]);
            }
        __syncwarp();

        // ---- B fragments (L1-resident after first iter) ----
        uint2 bf[16];
#pragma unroll
        for (int t = 0; t < 16; ++t) bf[t] = BFG[t * 32 + lane];

        // ---- layer 1 MMA + fused layer 2 epilogue ----
        u64 rs2[4];
#pragma unroll
        for (int j = 0; j < 4; ++j) rs2[j] = pk2(0.0f, 0.0f);

#pragma unroll
        for (int nt = 0; nt < 4; ++nt) {
#pragma unroll
            for (int mt = 0; mt < 2; ++mt) {
                float d[4] = {0.0f, 0.0f, 0.0f, 0.0f};
                mma_bf16(d, AH[mt][0], bf[0 + nt]);        // Z_hi @ W_hi (k0)
                mma_bf16(d, AH[mt][1], bf[4 + nt]);        // Z_hi @ W_hi (k1)
                mma_bf16(d, AL[mt][0], bf[0 + nt]);        // Z_lo @ W_hi (k0)
                mma_bf16(d, AL[mt][1], bf[4 + nt]);        // Z_lo @ W_hi (k1)
                mma_bf16(d, AH[mt][0], bf[8 + nt]);        // Z_hi @ W_lo (k0)
                mma_bf16(d, AH[mt][1], bf[12 + nt]);       // Z_hi @ W_lo (k1)

                // rows lane/4 + 16mt (+8) ; cols 8nt + 2(lane&3) + {0,1}
                float t0 = tanh_approx(d[0] + b1c[2 * nt]);
                float t1 = tanh_approx(d[1] + b1c[2 * nt + 1]);
                rs2[2 * mt] = ffma2(pk2(w2c[2 * nt], w2c[2 * nt + 1]),
                                    pk2(t0, t1), rs2[2 * mt]);
                float t2 = tanh_approx(d[2] + b1c[2 * nt]);
                float t3 = tanh_approx(d[3] + b1c[2 * nt + 1]);
                rs2[2 * mt + 1] = ffma2(pk2(w2c[2 * nt], w2c[2 * nt + 1]),
                                        pk2(t2, t3), rs2[2 * mt + 1]);
            }
        }

        // ---- quad reduce (cols spread over lane&3) + store ----
        float rs[4];
#pragma unroll
        for (int j = 0; j < 4; ++j) {
            float2 p = upk2(rs2[j]);
            float v = p.x + p.y;
            v += __shfl_xor_sync(0xffffffffu, v, 1);
            v += __shfl_xor_sync(0xffffffffu, v, 2);
            rs[j] = v;
        }
        const int row = (lane >> 2) + 8 * (lane & 3);
        out[sbase + row] = rs[lane & 3] + b2v;
    }
}

extern "C" void kernel_launch(void* const* d_in, const int* in_sizes, int n_in,
                              void* d_out, int out_size)
{
    const float* q  = (const float*)d_in[0];
    const float* w0 = (const float*)d_in[1];
    const float* b0 = (const float*)d_in[2];
    const float* w1 = (const float*)d_in[3];
    const float* b1 = (const float*)d_in[4];
    const float* w2 = (const float*)d_in[5];
    const float* b2 = (const float*)d_in[6];
    float* out = (float*)d_out;

    prep_kernel<<<17, TPB>>>(w0, b0, w1, b1, w2, b2);

    void* sym = nullptr; void* stg = nullptr;
    cudaGetSymbolAddress(&sym, CW4);
    cudaGetSymbolAddress(&stg, DSTG);
    cudaMemcpyAsync(sym, stg, 1348 * sizeof(float), cudaMemcpyDeviceToDevice);

    const int B = in_sizes[0] / NIN;                 // 2097152
    const int blocks = B / (TPB * ITERS);            // 4096
    WarpTileMLP_kernel<<<blocks, TPB>>>(q, out);
}